// round 9
// baseline (speedup 1.0000x reference)
#include <cuda_runtime.h>
#include <stdint.h>

// HSTU jagged causal attention — mma.sync tf32, register-resident P,
// one __syncthreads per tile iteration, double-buffered cp.async K/V.
//   out[i] = sum_{j<=i} silu(q_i.k_j/sqrt(D))/max_seqlen * v_j  per (seq,head)
// H=8, D=DV=128, B=8, max_seqlen=1024.
//
// CTA: 64-row Q tile x (head,batch), 128 threads = 4 warps.
// Warp w owns rows 16w..16w+15 FULL WIDTH:
//   MMA1: m16 x n32 x k128 (A=Q ldmatrix, B=K ldmatrix + RNA cvt)
//   P:    S C-frags -> silu -> shfl-transpose -> MMA2 A-frags (registers only)
//   MMA2: m16 x dv128 x k32 (A=P regs, B=V scalar LDS + RNA cvt)
// smem: Q[64x128] tf32 32KB, K 2x[32x128] raw 16KB, V 2x[32x128] raw 16KB = 96KB
// -> 2 CTAs/SM. Swizzles (16B chunk): Q/K c^(row&7); V c^((row&3)<<1).
// Loop: wait_group 0; __syncthreads; cp.async K,V(jt+1); MMA1; epi; MMA2.

#define HD    1024
#define NTH   128
#define BM    64
#define BN    32
#define NTILES 15
#define ALPHA 0.08838834764831845f

// smem byte offsets
#define SB_K   32768
#define SB_V   65536
#define KSTGB  16384
#define SMEM_BYTES 98304   // 96 KB

__device__ __forceinline__ uint32_t to_tf32(float f) {
    uint32_t r;
    asm("cvt.rna.tf32.f32 %0, %1;" : "=r"(r) : "f"(f));
    return r;
}
__device__ __forceinline__ uint32_t to_tf32_b(uint32_t bits) {
    uint32_t r;
    asm("cvt.rna.tf32.f32 %0, %1;" : "=r"(r) : "f"(__uint_as_float(bits)));
    return r;
}
__device__ __forceinline__ void mma_tf32(float* c, const uint32_t* a,
                                         uint32_t b0, uint32_t b1) {
    asm volatile(
        "mma.sync.aligned.m16n8k8.row.col.f32.tf32.tf32.f32 "
        "{%0,%1,%2,%3}, {%4,%5,%6,%7}, {%8,%9}, {%0,%1,%2,%3};"
        : "+f"(c[0]), "+f"(c[1]), "+f"(c[2]), "+f"(c[3])
        : "r"(a[0]), "r"(a[1]), "r"(a[2]), "r"(a[3]), "r"(b0), "r"(b1));
}
__device__ __forceinline__ void ldsm4(uint32_t* d, uint32_t addr) {
    asm volatile("ldmatrix.sync.aligned.m8n8.x4.shared.b16 {%0,%1,%2,%3}, [%4];"
                 : "=r"(d[0]), "=r"(d[1]), "=r"(d[2]), "=r"(d[3]) : "r"(addr));
}
__device__ __forceinline__ uint32_t smem_u32(const void* p) {
    uint32_t a;
    asm("{ .reg .u64 t; cvta.to.shared.u64 t, %1; cvt.u32.u64 %0, t; }"
        : "=r"(a) : "l"(p));
    return a;
}
__device__ __forceinline__ void cpa16(uint32_t dst, const float* src, int srcsz) {
    asm volatile("cp.async.cg.shared.global [%0], [%1], 16, %2;"
                 :: "r"(dst), "l"(src), "r"(srcsz) : "memory");
}
#define CPA_COMMIT() asm volatile("cp.async.commit_group;" ::: "memory")
#define CPA_WAIT0()  asm volatile("cp.async.wait_group 0;" ::: "memory")

__global__ void __launch_bounds__(NTH, 2)
hstu_regp_kernel(const float* __restrict__ tq, const float* __restrict__ tk,
                 const float* __restrict__ tv, const int* __restrict__ offsets,
                 const int* __restrict__ p_msl, const int* __restrict__ p_ssl,
                 float* __restrict__ out)
{
    extern __shared__ float smf[];
    float* Qs = smf;                       // tf32 bits, [64][128], chunk^ (r&7)
    const uint32_t smu = smem_u32(smf);

    const int b  = blockIdx.z;
    const int h  = blockIdx.y;
    const int it = (int)gridDim.x - 1 - (int)blockIdx.x;   // big tiles first

    const int off = offsets[b];
    const int len = offsets[b + 1] - off;
    const int i0  = it * BM;
    if (i0 >= len) return;

    const int msl = p_msl ? *p_msl : 1024;
    const int ssl = p_ssl ? *p_ssl : -1;
    const float rdenom = 1.0f / (float)((ssl > 0) ? ssl : msl);
    const float c_a = 0.5f * ALPHA;
    const float c_b = 0.5f * ALPHA * rdenom;

    const int tid  = threadIdx.x;
    const int w    = tid >> 5;
    const int lane = tid & 31;
    const int g    = lane >> 2;      // 0..7
    const int t4   = lane & 3;       // 0..3
    const int g3   = g & 3;
    const int gh   = g >> 2;
    const int xv   = t4 << 1;        // V swizzle term
    const int lq   = lane >> 3;
    const int lr   = lane & 7;

    // ldmatrix lane addressing
    const int arow = (w << 4) + ((lq & 1) << 3) + lr;   // Q A rows (m16)
    const int ac   = lq >> 1;
    const uint32_t qA = smu + (uint32_t)arow * 512;
    const int krow = ((lq >> 1) << 3) + lr;             // K B rows
    const int kc   = lq & 1;

    // shfl sources for C->A transpose
    const int srcA = (lane & ~3) | (t4 >> 1);
    const int srcB = srcA + 2;

    const float* kb = tk + (size_t)off * HD + h * 128;
    const float* vb = tv + (size_t)off * HD + h * 128;

    const int nj = min(2 * it + 2, (len + BN - 1) >> 5);

    // ---- prologue: cp.async K0,V0 (stage 0) + Q load ----
    {
        #pragma unroll
        for (int i2 = 0; i2 < 8; ++i2) {
            int idx = i2 * NTH + tid;  int r = idx >> 5;  int c = idx & 31;
            int ok = (r < len) ? 16 : 0;
            cpa16(smu + SB_K + (uint32_t)(r * 512 + ((c ^ (r & 7)) << 4)),
                  kb + (size_t)(ok ? r : 0) * HD + c * 4, ok);
        }
        #pragma unroll
        for (int i2 = 0; i2 < 8; ++i2) {
            int idx = i2 * NTH + tid;  int r = idx >> 5;  int c = idx & 31;
            int ok = (r < len) ? 16 : 0;
            cpa16(smu + SB_V + (uint32_t)(r * 512 + ((c ^ ((r & 3) << 1)) << 4)),
                  vb + (size_t)(ok ? r : 0) * HD + c * 4, ok);
        }
        CPA_COMMIT();

        const float* qb = tq + (size_t)off * HD + h * 128;
        #pragma unroll
        for (int i2 = 0; i2 < 16; ++i2) {
            int idx = i2 * NTH + tid;  int r = idx >> 5;  int c = idx & 31;
            float4 v = make_float4(0.f, 0.f, 0.f, 0.f);
            if (i0 + r < len)
                v = *(const float4*)(qb + (size_t)(i0 + r) * HD + c * 4);
            uint4 t;
            t.x = to_tf32(v.x); t.y = to_tf32(v.y);
            t.z = to_tf32(v.z); t.w = to_tf32(v.w);
            *(uint4*)(Qs + r * 128 + ((c ^ (r & 7)) << 2)) = t;
        }
    }

    float oacc[16][4];
    #pragma unroll
    for (int n = 0; n < 16; ++n)
        #pragma unroll
        for (int e = 0; e < 4; ++e) oacc[n][e] = 0.f;

    const int gia = i0 + (w << 4) + g;     // rows for a0/a2
    const int gib = gia + 8;               // rows for a1/a3

    for (int jt = 0; jt < nj; ++jt) {
        const int j0 = jt * BN;
        const int st = jt & 1;
        const uint32_t kB  = smu + SB_K + (uint32_t)st * KSTGB;
        const float*   Vst = smf + (SB_V >> 2) + st * (KSTGB >> 2);

        CPA_WAIT0();              // {K,V}(jt) landed
        __syncthreads();          // everyone done with iter jt-1 buffers

        // ---- prefetch {K,V}(jt+1) into other stage (read at jt-1, free) ----
        if (jt + 1 < nj) {
            const int j1 = j0 + BN;
            const uint32_t ko = SB_K + (uint32_t)(st ^ 1) * KSTGB;
            const uint32_t vo = SB_V + (uint32_t)(st ^ 1) * KSTGB;
            #pragma unroll
            for (int i2 = 0; i2 < 8; ++i2) {
                int idx = i2 * NTH + tid;  int r = idx >> 5;  int c = idx & 31;
                int gr = j1 + r;  int ok = (gr < len) ? 16 : 0;
                cpa16(smu + ko + (uint32_t)(r * 512 + ((c ^ (r & 7)) << 4)),
                      kb + (size_t)(ok ? gr : 0) * HD + c * 4, ok);
            }
            #pragma unroll
            for (int i2 = 0; i2 < 8; ++i2) {
                int idx = i2 * NTH + tid;  int r = idx >> 5;  int c = idx & 31;
                int gr = j1 + r;  int ok = (gr < len) ? 16 : 0;
                cpa16(smu + vo + (uint32_t)(r * 512 + ((c ^ ((r & 3) << 1)) << 4)),
                      vb + (size_t)(ok ? gr : 0) * HD + c * 4, ok);
            }
        }
        CPA_COMMIT();

        // ---- MMA1: S[m16 x n32] = Q K^T, k=128 ----
        float sacc[4][4];
        #pragma unroll
        for (int n = 0; n < 4; ++n)
            #pragma unroll
            for (int e = 0; e < 4; ++e) sacc[n][e] = 0.f;

        #pragma unroll
        for (int ks = 0; ks < 16; ++ks) {
            const int c2 = 2 * ks;
            uint32_t a[4], b0[4], b1[4];
            ldsm4(a,  qA + (uint32_t)(((c2 + ac) ^ lr) << 4));
            ldsm4(b0, kB + (uint32_t)(krow * 512        + (((c2 + kc) ^ lr) << 4)));
            ldsm4(b1, kB + (uint32_t)((krow + 16) * 512 + (((c2 + kc) ^ lr) << 4)));
            b0[0] = to_tf32_b(b0[0]); b0[1] = to_tf32_b(b0[1]);
            b0[2] = to_tf32_b(b0[2]); b0[3] = to_tf32_b(b0[3]);
            b1[0] = to_tf32_b(b1[0]); b1[1] = to_tf32_b(b1[1]);
            b1[2] = to_tf32_b(b1[2]); b1[3] = to_tf32_b(b1[3]);
            mma_tf32(sacc[0], a, b0[0], b0[1]);   // n 0-7
            mma_tf32(sacc[1], a, b0[2], b0[3]);   // n 8-15
            mma_tf32(sacc[2], a, b1[0], b1[1]);   // n 16-23
            mma_tf32(sacc[3], a, b1[2], b1[3]);   // n 24-31
        }

        // ---- silu on C-frags, shfl-transpose to A-frags, mask, cvt ----
        uint32_t pf[4][4];
        const int needmask = (jt >= 2 * it);
        #pragma unroll
        for (int f = 0; f < 4; ++f) {
            float p[4];
            #pragma unroll
            for (int e = 0; e < 4; ++e) {
                float s = sacc[f][e];
                float t;
                asm("tanh.approx.f32 %0, %1;" : "=f"(t) : "f"(s * c_a));
                float hx = s * c_b;
                p[e] = fmaf(hx, t, hx);
            }
            // C cols {2t4, 2t4+1} -> A cols {t4} and {t4+4}
            float s0 = __shfl_sync(0xffffffffu, p[0], srcA);
            float s1 = __shfl_sync(0xffffffffu, p[1], srcA);
            float a0 = (t4 & 1) ? s1 : s0;
            float s2 = __shfl_sync(0xffffffffu, p[0], srcB);
            float s3 = __shfl_sync(0xffffffffu, p[1], srcB);
            float a2 = (t4 & 1) ? s3 : s2;
            float s4 = __shfl_sync(0xffffffffu, p[2], srcA);
            float s5 = __shfl_sync(0xffffffffu, p[3], srcA);
            float a1 = (t4 & 1) ? s5 : s4;
            float s6 = __shfl_sync(0xffffffffu, p[2], srcB);
            float s7 = __shfl_sync(0xffffffffu, p[3], srcB);
            float a3 = (t4 & 1) ? s7 : s6;
            if (needmask) {
                const int jlo = j0 + 8 * f + t4;
                const int jhi = jlo + 4;
                a0 = (gia >= jlo) ? a0 : 0.f;
                a1 = (gib >= jlo) ? a1 : 0.f;
                a2 = (gia >= jhi) ? a2 : 0.f;
                a3 = (gib >= jhi) ? a3 : 0.f;
            }
            pf[f][0] = to_tf32(a0); pf[f][1] = to_tf32(a1);
            pf[f][2] = to_tf32(a2); pf[f][3] = to_tf32(a3);
        }

        // ---- MMA2: O[m16 x dv128] += P V, k=32 ----
        #pragma unroll
        for (int f = 0; f < 4; ++f) {
            const float* vr  = Vst + (8 * f + t4) * 128;   // j row t4-part
            const float* vr4 = vr + 4 * 128;               // j row +4
            #pragma unroll
            for (int nf = 0; nf < 16; ++nf) {
                const int vo = (((2 * nf + gh) ^ xv) << 2) + g3;
                uint32_t b0 = to_tf32(vr[vo]);
                uint32_t b1 = to_tf32(vr4[vo]);
                mma_tf32(oacc[nf], pf[f], b0, b1);
            }
        }
    }

    // ---- store O: rows gia/gib, cols 8nf + 2t4 ----
    {
        float* ob0 = out + (size_t)(off + gia) * HD + h * 128 + 2 * t4;
        float* ob1 = out + (size_t)(off + gib) * HD + h * 128 + 2 * t4;
        #pragma unroll
        for (int nf = 0; nf < 16; ++nf) {
            if (gia < len) {
                float2 v; v.x = oacc[nf][0]; v.y = oacc[nf][1];
                *(float2*)(ob0 + nf * 8) = v;
            }
            if (gib < len) {
                float2 v; v.x = oacc[nf][2]; v.y = oacc[nf][3];
                *(float2*)(ob1 + nf * 8) = v;
            }
        }
    }
}

extern "C" void kernel_launch(void* const* d_in, const int* in_sizes, int n_in,
                              void* d_out, int out_size)
{
    const float* tq      = (const float*)d_in[0];
    const float* tk      = (const float*)d_in[1];
    const float* tv      = (const float*)d_in[2];
    const int*   offsets = (const int*)  d_in[3];
    const int*   p_msl   = (n_in > 4) ? (const int*)d_in[4] : nullptr;
    const int*   p_ssl   = (n_in > 5) ? (const int*)d_in[5] : nullptr;
    float*       out     = (float*)d_out;

    const int B = in_sizes[3] - 1;

    cudaFuncSetAttribute((const void*)hstu_regp_kernel,
                         cudaFuncAttributeMaxDynamicSharedMemorySize, SMEM_BYTES);

    dim3 grid(NTILES, 8, B);
    hstu_regp_kernel<<<grid, NTH, SMEM_BYTES>>>(tq, tk, tv, offsets,
                                                p_msl, p_ssl, out);
}

// round 10
// speedup vs baseline: 1.7071x; 1.7071x over previous
#include <cuda_runtime.h>
#include <cuda_fp16.h>
#include <stdint.h>

// HSTU jagged causal attention — fp16 mma.sync (m16n8k16) + ldmatrix(.trans),
// cp.async double-buffered K/V, 2 barriers/iter, 2 CTAs/SM (88KB smem).
// A separate bandwidth-bound kernel pre-converts K/V fp32->fp16 into
// __device__ scratch so the main loop has zero conversion instructions.
//   out[i] = sum_{j<=i} silu(q_i.k_j/sqrt(D))/max_seqlen * v_j  per (seq,head)
// H=8, D=DV=128, B=8, max_seqlen=1024.
//
// CTA: 64-row Q tile x (head,batch), 128 threads = 4 warps, warp (mh,nh):
//  MMA1: m32 x n32 x k128  (A=Q ldsm, B=K ldsm)        -> 64 mma, 32 ldsm
//  P:    silu(C-frags) -> fp16 -> smem (STS.32, conflict-free)
//  MMA2: m32 x dv64 x k64  (A=P ldsm, B=V ldsm.trans)  -> 64 mma, 24 ldsm
// Smem rows are 256B (Q/K/V) or 128B (P); 16B-chunk swizzle c^(row&7)
// makes every cp.async STS, manual STS and ldmatrix phase conflict-free.

#define HD    1024
#define NTH   128
#define NTILES 16
#define ALPHA 0.08838834764831845f

// smem byte offsets
#define SB_Q  0
#define SB_K  16384
#define KSTG  16384
#define SB_V  49152
#define SB_P  81920
#define SMEM_BYTES 90112       // 88 KB

__device__ __align__(16) __half g_kh[(size_t)8192 * 1024];
__device__ __align__(16) __half g_vh[(size_t)8192 * 1024];

__global__ void __launch_bounds__(256)
cvt_kernel(const float* __restrict__ k, const float* __restrict__ v, int n4)
{
    int i = blockIdx.x * 256 + threadIdx.x;
    if (i >= n4) return;
    float4 a = ((const float4*)k)[i];
    float4 b = ((const float4*)v)[i];
    __half2 h0 = __floats2half2_rn(a.x, a.y);
    __half2 h1 = __floats2half2_rn(a.z, a.w);
    __half2 h2 = __floats2half2_rn(b.x, b.y);
    __half2 h3 = __floats2half2_rn(b.z, b.w);
    uint2 wk, wv;
    wk.x = *(uint32_t*)&h0;  wk.y = *(uint32_t*)&h1;
    wv.x = *(uint32_t*)&h2;  wv.y = *(uint32_t*)&h3;
    ((uint2*)g_kh)[i] = wk;
    ((uint2*)g_vh)[i] = wv;
}

__device__ __forceinline__ void mma_f16(float* c, const uint32_t* a,
                                        uint32_t b0, uint32_t b1) {
    asm volatile(
        "mma.sync.aligned.m16n8k16.row.col.f32.f16.f16.f32 "
        "{%0,%1,%2,%3}, {%4,%5,%6,%7}, {%8,%9}, {%0,%1,%2,%3};"
        : "+f"(c[0]), "+f"(c[1]), "+f"(c[2]), "+f"(c[3])
        : "r"(a[0]), "r"(a[1]), "r"(a[2]), "r"(a[3]), "r"(b0), "r"(b1));
}
__device__ __forceinline__ void ldsm4(uint32_t* d, uint32_t addr) {
    asm volatile("ldmatrix.sync.aligned.m8n8.x4.shared.b16 {%0,%1,%2,%3}, [%4];"
                 : "=r"(d[0]), "=r"(d[1]), "=r"(d[2]), "=r"(d[3]) : "r"(addr));
}
__device__ __forceinline__ void ldsm4t(uint32_t* d, uint32_t addr) {
    asm volatile("ldmatrix.sync.aligned.m8n8.x4.trans.shared.b16 {%0,%1,%2,%3}, [%4];"
                 : "=r"(d[0]), "=r"(d[1]), "=r"(d[2]), "=r"(d[3]) : "r"(addr));
}
__device__ __forceinline__ uint32_t smem_u32(const void* p) {
    uint32_t a;
    asm("{ .reg .u64 t; cvta.to.shared.u64 t, %1; cvt.u32.u64 %0, t; }"
        : "=r"(a) : "l"(p));
    return a;
}
__device__ __forceinline__ void cpa16(uint32_t dst, const __half* src, int srcsz) {
    asm volatile("cp.async.cg.shared.global [%0], [%1], 16, %2;"
                 :: "r"(dst), "l"(src), "r"(srcsz) : "memory");
}
#define CPA_COMMIT() asm volatile("cp.async.commit_group;" ::: "memory")
#define CPA_WAIT0()  asm volatile("cp.async.wait_group 0;" ::: "memory")

__global__ void __launch_bounds__(NTH, 2)
hstu_f16_kernel(const float* __restrict__ tq, const int* __restrict__ offsets,
                const int* __restrict__ p_msl, const int* __restrict__ p_ssl,
                float* __restrict__ out)
{
    extern __shared__ char smc[];
    const uint32_t smu = smem_u32(smc);

    const int b  = blockIdx.z;
    const int h  = blockIdx.y;
    const int it = (int)gridDim.x - 1 - (int)blockIdx.x;   // big tiles first

    const int off = offsets[b];
    const int len = offsets[b + 1] - off;
    const int i0  = it * 64;
    if (i0 >= len) return;

    const int msl = p_msl ? *p_msl : 1024;
    const int ssl = p_ssl ? *p_ssl : -1;
    const float rdenom = 1.0f / (float)((ssl > 0) ? ssl : msl);
    const float c_a = 0.5f * ALPHA;
    const float c_b = 0.5f * ALPHA * rdenom;

    const int tid  = threadIdx.x;
    const int w    = tid >> 5;
    const int lane = tid & 31;
    const int g    = lane >> 2;
    const int t4   = lane & 3;
    const int lq   = lane >> 3;
    const int lr   = lane & 7;
    const int mh   = w & 1;
    const int nh   = w >> 1;

    // ldmatrix lane bases (row&7 == lr for every operand, so xor term = lr)
    const int ac  = lq >> 1;                               // A chunk add
    const int kc2 = lq & 1;                                // K-B chunk add
    const uint32_t qA0 = smu + SB_Q + (uint32_t)(mh * 32 + ((lq & 1) << 3) + lr) * 256;
    const uint32_t qA1 = qA0 + 16 * 256;
    const int krow     = nh * 32 + ((lq >> 1) << 3) + lr;  // K rows
    const uint32_t pA0 = smu + SB_P + (uint32_t)(mh * 32 + ((lq & 1) << 3) + lr) * 128;
    const uint32_t pA1 = pA0 + 16 * 128;
    const int vrow0    = ((lq & 1) << 3) + lr;             // V row within k16 group
    const int vc       = lq >> 1;                          // V chunk add

    const __half* kb = g_kh + (size_t)off * HD + h * 128;
    const __half* vb = g_vh + (size_t)off * HD + h * 128;

    const int nj = it + 1;

    // ---- prologue: cp.async K0,V0 (stage 0); Q load fp32->fp16 swizzled ----
    #pragma unroll
    for (int i2 = 0; i2 < 8; ++i2) {
        int idx = i2 * NTH + tid;  int r = idx >> 4;  int c = idx & 15;
        int ok = (r < len) ? 16 : 0;
        cpa16(smu + SB_K + (uint32_t)(r * 256 + ((c ^ (r & 7)) << 4)),
              kb + (size_t)(ok ? r : 0) * HD + c * 8, ok);
        cpa16(smu + SB_V + (uint32_t)(r * 256 + ((c ^ (r & 7)) << 4)),
              vb + (size_t)(ok ? r : 0) * HD + c * 8, ok);
    }
    CPA_COMMIT();
    {
        const float* qb = tq + (size_t)off * HD + h * 128;
        #pragma unroll
        for (int i2 = 0; i2 < 8; ++i2) {
            int idx = i2 * NTH + tid;  int r = idx >> 4;  int c = idx & 15;
            float4 v0 = make_float4(0.f, 0.f, 0.f, 0.f);
            float4 v1 = make_float4(0.f, 0.f, 0.f, 0.f);
            if (i0 + r < len) {
                const float* qr = qb + (size_t)(i0 + r) * HD + c * 8;
                v0 = *(const float4*)(qr);
                v1 = *(const float4*)(qr + 4);
            }
            __half2 h0 = __floats2half2_rn(v0.x, v0.y);
            __half2 h1 = __floats2half2_rn(v0.z, v0.w);
            __half2 h2 = __floats2half2_rn(v1.x, v1.y);
            __half2 h3 = __floats2half2_rn(v1.z, v1.w);
            uint4 t;
            t.x = *(uint32_t*)&h0; t.y = *(uint32_t*)&h1;
            t.z = *(uint32_t*)&h2; t.w = *(uint32_t*)&h3;
            *(uint4*)(smc + SB_Q + r * 256 + ((c ^ (r & 7)) << 4)) = t;
        }
    }

    float oacc[2][8][4];
    #pragma unroll
    for (int a = 0; a < 2; ++a)
        #pragma unroll
        for (int n = 0; n < 8; ++n)
            #pragma unroll
            for (int e = 0; e < 4; ++e) oacc[a][n][e] = 0.f;

    for (int jt = 0; jt < nj; ++jt) {
        const int j0 = jt * 64;
        const int st = jt & 1;
        const uint32_t kBs = smu + SB_K + (uint32_t)st * KSTG;
        const uint32_t vBs = smu + SB_V + (uint32_t)st * KSTG;

        CPA_WAIT0();              // my chunks of K/V[jt] done
        __syncthreads();          // tile visible; st^1 free (jt-1 reads done)

        // prefetch {K,V}[jt+1] into the other stage
        if (jt + 1 < nj) {
            const int j1 = j0 + 64;
            const uint32_t ko = SB_K + (uint32_t)(st ^ 1) * KSTG;
            const uint32_t vo = SB_V + (uint32_t)(st ^ 1) * KSTG;
            #pragma unroll
            for (int i2 = 0; i2 < 8; ++i2) {
                int idx = i2 * NTH + tid;  int r = idx >> 4;  int c = idx & 15;
                int gr = j1 + r;  int ok = (gr < len) ? 16 : 0;
                cpa16(smu + ko + (uint32_t)(r * 256 + ((c ^ (r & 7)) << 4)),
                      kb + (size_t)(ok ? gr : 0) * HD + c * 8, ok);
                cpa16(smu + vo + (uint32_t)(r * 256 + ((c ^ (r & 7)) << 4)),
                      vb + (size_t)(ok ? gr : 0) * HD + c * 8, ok);
            }
        }
        CPA_COMMIT();

        // ---- MMA1: S[m32 x n32] = Q K^T, k=128 (8 k16 steps) ----
        float sacc[2][4][4];
        #pragma unroll
        for (int a = 0; a < 2; ++a)
            #pragma unroll
            for (int n = 0; n < 4; ++n)
                #pragma unroll
                for (int e = 0; e < 4; ++e) sacc[a][n][e] = 0.f;

        #pragma unroll
        for (int ks = 0; ks < 8; ++ks) {
            const int kc = 2 * ks;
            uint32_t a0[4], a1[4], b0[4], b1[4];
            ldsm4(a0, qA0 + (uint32_t)(((kc + ac) ^ lr) << 4));
            ldsm4(a1, qA1 + (uint32_t)(((kc + ac) ^ lr) << 4));
            ldsm4(b0, kBs + (uint32_t)(krow * 256        + (((kc + kc2) ^ lr) << 4)));
            ldsm4(b1, kBs + (uint32_t)((krow + 16) * 256 + (((kc + kc2) ^ lr) << 4)));
            mma_f16(sacc[0][0], a0, b0[0], b0[1]);
            mma_f16(sacc[0][1], a0, b0[2], b0[3]);
            mma_f16(sacc[0][2], a0, b1[0], b1[1]);
            mma_f16(sacc[0][3], a0, b1[2], b1[3]);
            mma_f16(sacc[1][0], a1, b0[0], b0[1]);
            mma_f16(sacc[1][1], a1, b0[2], b0[3]);
            mma_f16(sacc[1][2], a1, b1[0], b1[1]);
            mma_f16(sacc[1][3], a1, b1[2], b1[3]);
        }

        // ---- silu + (diag) causal mask -> P fp16 in smem ----
        const int diag = (jt == it);
        #pragma unroll
        for (int mf = 0; mf < 2; ++mf) {
            const int r0  = mh * 32 + mf * 16 + g;
            const int gi0 = i0 + r0;
            #pragma unroll
            for (int nf = 0; nf < 4; ++nf) {
                const int jl = nh * 32 + 8 * nf;
                float p[4];
                #pragma unroll
                for (int e = 0; e < 4; ++e) {
                    float s = sacc[mf][nf][e];
                    float t;
                    asm("tanh.approx.f32 %0, %1;" : "=f"(t) : "f"(s * c_a));
                    float hx = s * c_b;
                    p[e] = fmaf(hx, t, hx);
                }
                if (diag) {
                    const int jc = j0 + jl + 2 * t4;
                    p[0] = (gi0     >= jc)     ? p[0] : 0.f;
                    p[1] = (gi0     >= jc + 1) ? p[1] : 0.f;
                    p[2] = (gi0 + 8 >= jc)     ? p[2] : 0.f;
                    p[3] = (gi0 + 8 >= jc + 1) ? p[3] : 0.f;
                }
                __half2 h01 = __floats2half2_rn(p[0], p[1]);
                __half2 h23 = __floats2half2_rn(p[2], p[3]);
                const int pc = (jl >> 3) ^ g;              // swizzled chunk
                char* pp = smc + SB_P + r0 * 128 + (pc << 4) + t4 * 4;
                *(uint32_t*)(pp)            = *(uint32_t*)&h01;
                *(uint32_t*)(pp + 8 * 128)  = *(uint32_t*)&h23;
            }
        }
        __syncthreads();          // P visible to all warps

        // ---- MMA2: O[m32 x dv64] += P V, k=64 (4 k16 steps) ----
        #pragma unroll
        for (int ks = 0; ks < 4; ++ks) {
            const int jc = 2 * ks;
            uint32_t a0[4], a1[4];
            ldsm4(a0, pA0 + (uint32_t)(((jc + ac) ^ lr) << 4));
            ldsm4(a1, pA1 + (uint32_t)(((jc + ac) ^ lr) << 4));
            const int vrow = 16 * ks + vrow0;
            const uint32_t vba = vBs + (uint32_t)vrow * 256;
            #pragma unroll
            for (int q = 0; q < 4; ++q) {
                const int cd = 8 * nh + 2 * q;
                uint32_t bv[4];
                ldsm4t(bv, vba + (uint32_t)(((cd + vc) ^ lr) << 4));
                mma_f16(oacc[0][2 * q],     a0, bv[0], bv[1]);
                mma_f16(oacc[0][2 * q + 1], a0, bv[2], bv[3]);
                mma_f16(oacc[1][2 * q],     a1, bv[0], bv[1]);
                mma_f16(oacc[1][2 * q + 1], a1, bv[2], bv[3]);
            }
        }
    }

    // ---- store O: rows mh*32+mf*16+g (+8), cols nh*64 + 8nf + 2t4 ----
    #pragma unroll
    for (int mf = 0; mf < 2; ++mf) {
        const int r0 = i0 + mh * 32 + mf * 16 + g;
        const int r1 = r0 + 8;
        float* ob0 = out + (size_t)(off + r0) * HD + h * 128 + nh * 64 + 2 * t4;
        float* ob1 = out + (size_t)(off + r1) * HD + h * 128 + nh * 64 + 2 * t4;
        #pragma unroll
        for (int nf = 0; nf < 8; ++nf) {
            if (r0 < len) {
                float2 v; v.x = oacc[mf][nf][0]; v.y = oacc[mf][nf][1];
                *(float2*)(ob0 + nf * 8) = v;
            }
            if (r1 < len) {
                float2 v; v.x = oacc[mf][nf][2]; v.y = oacc[mf][nf][3];
                *(float2*)(ob1 + nf * 8) = v;
            }
        }
    }
}

extern "C" void kernel_launch(void* const* d_in, const int* in_sizes, int n_in,
                              void* d_out, int out_size)
{
    const float* tq      = (const float*)d_in[0];
    const float* tk      = (const float*)d_in[1];
    const float* tv      = (const float*)d_in[2];
    const int*   offsets = (const int*)  d_in[3];
    const int*   p_msl   = (n_in > 4) ? (const int*)d_in[4] : nullptr;
    const int*   p_ssl   = (n_in > 5) ? (const int*)d_in[5] : nullptr;
    float*       out     = (float*)d_out;

    const int B  = in_sizes[3] - 1;
    const int n4 = in_sizes[1] / 4;

    cvt_kernel<<<(n4 + 255) / 256, 256>>>(tk, tv, n4);

    cudaFuncSetAttribute((const void*)hstu_f16_kernel,
                         cudaFuncAttributeMaxDynamicSharedMemorySize, SMEM_BYTES);
    dim3 grid(NTILES, 8, B);
    hstu_f16_kernel<<<grid, NTH, SMEM_BYTES>>>(tq, offsets, p_msl, p_ssl, out);
}